// round 9
// baseline (speedup 1.0000x reference)
#include <cuda_runtime.h>

// GRU autoencoder: B=128, H=512, T=512 enc + 513 dec iterations.
// Persistent single kernel (one graph node). Trap-guarded monotonic grid
// barrier. 128 CTAs, CTA c owns hidden cols [4c,4c+4). Per step each CTA
// computes its 12 gate dots over the full previous h, plus (decoder) a
// redundant 13th dot y = h@lin_W.T per CTA -> no cross-CTA reduction.
// h double-buffered, transposed h[k][b]. Inner product uses packed
// fma.rn.f32x2: halves fma-pipe issue count.

#define HH   512
#define TT   512
#define BB   128
#define NBLK 128
#define COLS 4
#define NTH  256
#define KHALF 256

__device__ float g_hA[HH * BB];
__device__ float g_hB[HH * BB];
__device__ unsigned long long g_arrive;   // monotonic; replay-safe
__device__ unsigned long long g_release;

__device__ __forceinline__ void grid_barrier() {
    __threadfence();
    __syncthreads();
    if (threadIdx.x == 0) {
        unsigned long long t = atomicAdd(&g_arrive, 1ULL) + 1ULL;
        unsigned long long phase = (t + (unsigned long long)(NBLK - 1)) / NBLK;
        if ((t % NBLK) == 0ULL) {
            atomicAdd(&g_release, 1ULL);
        } else {
            long long guard = 0;
            while (*(volatile unsigned long long*)&g_release < phase) {
                __nanosleep(64);
                if (++guard > 300000000LL) __trap();   // fail loud, never hang
            }
        }
        __threadfence();
    }
    __syncthreads();
}

__device__ __forceinline__ float sigf(float v) { return 1.0f / (1.0f + __expf(-v)); }

__device__ __forceinline__ unsigned long long pack2(float lo, float hi) {
    unsigned long long r;
    asm("mov.b64 %0, {%1, %2};" : "=l"(r) : "f"(lo), "f"(hi));
    return r;
}
__device__ __forceinline__ unsigned long long fma2(unsigned long long a,
                                                   unsigned long long b,
                                                   unsigned long long c) {
    unsigned long long d;
    asm("fma.rn.f32x2 %0, %1, %2, %3;" : "=l"(d) : "l"(a), "l"(b), "l"(c));
    return d;
}
__device__ __forceinline__ float red2(unsigned long long v) {
    float lo, hi;
    asm("mov.b64 {%0, %1}, %2;" : "=f"(lo), "=f"(hi) : "l"(v));
    return lo + hi;
}

__global__ void __launch_bounds__(NTH, 1)
gru_ae(const float* __restrict__ x,
       const float* __restrict__ eWi, const float* __restrict__ eWh,
       const float* __restrict__ ebi, const float* __restrict__ ebh,
       const float* __restrict__ dWi, const float* __restrict__ dWh,
       const float* __restrict__ dbi, const float* __restrict__ dbh,
       const float* __restrict__ lW,  const float* __restrict__ lb,
       float* __restrict__ out)
{
    __shared__ __align__(16) float s_w[12 * HH];   // Wh rows: row = jj*3+gate
    __shared__ __align__(16) float s_lin[HH];
    __shared__ float s_red[13 * BB];
    __shared__ float s_wi[12], s_bi[12], s_bh[12];
    __shared__ float s_lb;

    const int tid = threadIdx.x;
    const int b   = tid & (BB - 1);
    const int kh  = tid >> 7;
    const int j0  = blockIdx.x * COLS;

    // ---- encoder weights -> SMEM (vectorized rows) ----
    for (int i = tid; i < 12 * (HH / 4); i += NTH) {
        int gl = i / (HH / 4), kq = i % (HH / 4);
        int grow = (gl % 3) * HH + (j0 + gl / 3);
        ((float4*)s_w)[gl * (HH / 4) + kq] = ((const float4*)eWh)[grow * (HH / 4) + kq];
    }
    for (int i = tid; i < HH / 4; i += NTH)
        ((float4*)s_lin)[i] = ((const float4*)lW)[i];
    if (tid < 12) {
        int grow = (tid % 3) * HH + (j0 + tid / 3);
        s_wi[tid] = eWi[grow];
        s_bi[tid] = ebi[grow];
        s_bh[tid] = ebh[grow];
    }
    if (tid == 0) s_lb = lb[0];        // BUGFIX R8: was tid==384 (> NTH) -> never ran

    for (int i = tid; i < COLS * BB; i += NTH) g_hA[j0 * BB + i] = 0.0f;

    grid_barrier();

    float* hcur = g_hA;
    float* hnxt = g_hB;

    // ================= encoder: 512 steps =================
    for (int t = 0; t < TT; ++t) {
        unsigned long long acc[12];
        #pragma unroll
        for (int g = 0; g < 12; ++g) acc[g] = 0ULL;

        const int k0 = kh * KHALF;
        #pragma unroll 2
        for (int k = k0; k < k0 + KHALF; k += 4) {
            float h0 = __ldcg(&hcur[(k + 0) * BB + b]);
            float h1 = __ldcg(&hcur[(k + 1) * BB + b]);
            float h2 = __ldcg(&hcur[(k + 2) * BB + b]);
            float h3 = __ldcg(&hcur[(k + 3) * BB + b]);
            unsigned long long ha = pack2(h0, h1);
            unsigned long long hb = pack2(h2, h3);
            #pragma unroll
            for (int g = 0; g < 12; ++g) {
                const ulonglong2 w2 = *(const ulonglong2*)&s_w[g * HH + k];
                acc[g] = fma2(ha, w2.x, acc[g]);
                acc[g] = fma2(hb, w2.y, acc[g]);
            }
        }

        if (kh) {
            #pragma unroll
            for (int g = 0; g < 12; ++g) s_red[g * BB + b] = red2(acc[g]);
        }
        __syncthreads();

        if (!kh) {
            float xv = x[b * TT + t];
            #pragma unroll
            for (int jj = 0; jj < COLS; ++jj) {
                float ar = red2(acc[jj * 3 + 0]) + s_red[(jj * 3 + 0) * BB + b];
                float az = red2(acc[jj * 3 + 1]) + s_red[(jj * 3 + 1) * BB + b];
                float an = red2(acc[jj * 3 + 2]) + s_red[(jj * 3 + 2) * BB + b];
                float r = sigf(fmaf(xv, s_wi[jj * 3 + 0], s_bi[jj * 3 + 0] + s_bh[jj * 3 + 0]) + ar);
                float z = sigf(fmaf(xv, s_wi[jj * 3 + 1], s_bi[jj * 3 + 1] + s_bh[jj * 3 + 1]) + az);
                float n = tanhf(fmaf(xv, s_wi[jj * 3 + 2], s_bi[jj * 3 + 2]) + r * (an + s_bh[jj * 3 + 2]));
                float hp = __ldcg(&hcur[(j0 + jj) * BB + b]);
                hnxt[(j0 + jj) * BB + b] = (1.0f - z) * n + z * hp;
            }
        }

        grid_barrier();
        float* tc = hcur; hcur = hnxt; hnxt = tc;
    }

    // ---- swap SMEM weights to decoder ----
    for (int i = tid; i < 12 * (HH / 4); i += NTH) {
        int gl = i / (HH / 4), kq = i % (HH / 4);
        int grow = (gl % 3) * HH + (j0 + gl / 3);
        ((float4*)s_w)[gl * (HH / 4) + kq] = ((const float4*)dWh)[grow * (HH / 4) + kq];
    }
    if (tid < 12) {
        int grow = (tid % 3) * HH + (j0 + tid / 3);
        s_wi[tid] = dWi[grow];
        s_bi[tid] = dbi[grow];
        s_bh[tid] = dbh[grow];
    }
    __syncthreads();

    // ================= decoder: i = 0..512 =================
    // y_i = h_i @ lin_W.T + lin_b (redundant per CTA). Emit y_i at
    // out[:, T-i] for i>=1. For i<512 also compute h_{i+1}.
    for (int i = 0; i <= TT; ++i) {
        unsigned long long acc[13];
        #pragma unroll
        for (int g = 0; g < 13; ++g) acc[g] = 0ULL;

        const int k0 = kh * KHALF;
        #pragma unroll 2
        for (int k = k0; k < k0 + KHALF; k += 4) {
            float h0 = __ldcg(&hcur[(k + 0) * BB + b]);
            float h1 = __ldcg(&hcur[(k + 1) * BB + b]);
            float h2 = __ldcg(&hcur[(k + 2) * BB + b]);
            float h3 = __ldcg(&hcur[(k + 3) * BB + b]);
            unsigned long long ha = pack2(h0, h1);
            unsigned long long hb = pack2(h2, h3);
            #pragma unroll
            for (int g = 0; g < 12; ++g) {
                const ulonglong2 w2 = *(const ulonglong2*)&s_w[g * HH + k];
                acc[g] = fma2(ha, w2.x, acc[g]);
                acc[g] = fma2(hb, w2.y, acc[g]);
            }
            const ulonglong2 l2 = *(const ulonglong2*)&s_lin[k];
            acc[12] = fma2(ha, l2.x, acc[12]);
            acc[12] = fma2(hb, l2.y, acc[12]);
        }

        if (kh) {
            #pragma unroll
            for (int g = 0; g < 13; ++g) s_red[g * BB + b] = red2(acc[g]);
        }
        __syncthreads();

        if (!kh) {
            float y = red2(acc[12]) + s_red[12 * BB + b] + s_lb;
            if (i >= 1 && blockIdx.x == 0) out[b * TT + (TT - i)] = y;
            if (i < TT) {
                #pragma unroll
                for (int jj = 0; jj < COLS; ++jj) {
                    float ar = red2(acc[jj * 3 + 0]) + s_red[(jj * 3 + 0) * BB + b];
                    float az = red2(acc[jj * 3 + 1]) + s_red[(jj * 3 + 1) * BB + b];
                    float an = red2(acc[jj * 3 + 2]) + s_red[(jj * 3 + 2) * BB + b];
                    float r = sigf(fmaf(y, s_wi[jj * 3 + 0], s_bi[jj * 3 + 0] + s_bh[jj * 3 + 0]) + ar);
                    float z = sigf(fmaf(y, s_wi[jj * 3 + 1], s_bi[jj * 3 + 1] + s_bh[jj * 3 + 1]) + az);
                    float n = tanhf(fmaf(y, s_wi[jj * 3 + 2], s_bi[jj * 3 + 2]) + r * (an + s_bh[jj * 3 + 2]));
                    float hp = __ldcg(&hcur[(j0 + jj) * BB + b]);
                    hnxt[(j0 + jj) * BB + b] = (1.0f - z) * n + z * hp;
                }
            }
        }

        if (i < TT) {
            grid_barrier();
            float* tc = hcur; hcur = hnxt; hnxt = tc;
        }
    }
}

extern "C" void kernel_launch(void* const* d_in, const int* in_sizes, int n_in,
                              void* d_out, int out_size) {
    gru_ae<<<NBLK, NTH>>>(
        (const float*)d_in[0],
        (const float*)d_in[1], (const float*)d_in[2],
        (const float*)d_in[3], (const float*)d_in[4],
        (const float*)d_in[5], (const float*)d_in[6],
        (const float*)d_in[7], (const float*)d_in[8],
        (const float*)d_in[9], (const float*)d_in[10],
        (float*)d_out);
}

// round 10
// speedup vs baseline: 1.2179x; 1.2179x over previous
#include <cuda_runtime.h>

// GRU autoencoder: B=128, H=512, T=512 enc + 513 dec iterations.
// Persistent single kernel (one graph node). Trap-guarded monotonic grid
// barrier. 128 CTAs, CTA c owns hidden cols [4c,4c+4).
//
// R9 -> R10: latency-bound (issue 26.9%, occ 12.5%). NTH 256->512:
// K split 4 ways (128/thread) so each SMSP holds 4 warps instead of 2.
// 3 quarters store partials to SMEM, quarter 0 combines + epilogue.

#define HH   512
#define TT   512
#define BB   128
#define NBLK 128
#define COLS 4
#define NTH  512
#define KQ   128      // K per thread

__device__ float g_hA[HH * BB];
__device__ float g_hB[HH * BB];
__device__ unsigned long long g_arrive;   // monotonic; replay-safe
__device__ unsigned long long g_release;

__device__ __forceinline__ void grid_barrier() {
    __threadfence();
    __syncthreads();
    if (threadIdx.x == 0) {
        unsigned long long t = atomicAdd(&g_arrive, 1ULL) + 1ULL;
        unsigned long long phase = (t + (unsigned long long)(NBLK - 1)) / NBLK;
        if ((t % NBLK) == 0ULL) {
            atomicAdd(&g_release, 1ULL);
        } else {
            long long guard = 0;
            while (*(volatile unsigned long long*)&g_release < phase) {
                __nanosleep(20);
                if (++guard > 900000000LL) __trap();   // fail loud, never hang
            }
        }
        __threadfence();
    }
    __syncthreads();
}

__device__ __forceinline__ float sigf(float v) { return 1.0f / (1.0f + __expf(-v)); }

__device__ __forceinline__ unsigned long long pack2(float lo, float hi) {
    unsigned long long r;
    asm("mov.b64 %0, {%1, %2};" : "=l"(r) : "f"(lo), "f"(hi));
    return r;
}
__device__ __forceinline__ unsigned long long fma2(unsigned long long a,
                                                   unsigned long long b,
                                                   unsigned long long c) {
    unsigned long long d;
    asm("fma.rn.f32x2 %0, %1, %2, %3;" : "=l"(d) : "l"(a), "l"(b), "l"(c));
    return d;
}
__device__ __forceinline__ float red2(unsigned long long v) {
    float lo, hi;
    asm("mov.b64 {%0, %1}, %2;" : "=f"(lo), "=f"(hi) : "l"(v));
    return lo + hi;
}

__global__ void __launch_bounds__(NTH, 1)
gru_ae(const float* __restrict__ x,
       const float* __restrict__ eWi, const float* __restrict__ eWh,
       const float* __restrict__ ebi, const float* __restrict__ ebh,
       const float* __restrict__ dWi, const float* __restrict__ dWh,
       const float* __restrict__ dbi, const float* __restrict__ dbh,
       const float* __restrict__ lW,  const float* __restrict__ lb,
       float* __restrict__ out)
{
    __shared__ __align__(16) float s_w[12 * HH];     // Wh rows: row = jj*3+gate
    __shared__ __align__(16) float s_lin[HH];
    __shared__ float s_red[3 * 13 * BB];             // partials from quarters 1..3
    __shared__ float s_wi[12], s_bi[12], s_bh[12];
    __shared__ float s_lb;

    const int tid = threadIdx.x;
    const int b   = tid & (BB - 1);
    const int kq  = tid >> 7;          // k-quarter: 0..3
    const int j0  = blockIdx.x * COLS;

    // ---- encoder weights -> SMEM (vectorized rows) ----
    for (int i = tid; i < 12 * (HH / 4); i += NTH) {
        int gl = i / (HH / 4), kk = i % (HH / 4);
        int grow = (gl % 3) * HH + (j0 + gl / 3);
        ((float4*)s_w)[gl * (HH / 4) + kk] = ((const float4*)eWh)[grow * (HH / 4) + kk];
    }
    for (int i = tid; i < HH / 4; i += NTH)
        ((float4*)s_lin)[i] = ((const float4*)lW)[i];
    if (tid < 12) {
        int grow = (tid % 3) * HH + (j0 + tid / 3);
        s_wi[tid] = eWi[grow];
        s_bi[tid] = ebi[grow];
        s_bh[tid] = ebh[grow];
    }
    if (tid == 0) s_lb = lb[0];

    for (int i = tid; i < COLS * BB; i += NTH) g_hA[j0 * BB + i] = 0.0f;

    grid_barrier();

    float* hcur = g_hA;
    float* hnxt = g_hB;

    // ================= encoder: 512 steps =================
    for (int t = 0; t < TT; ++t) {
        unsigned long long acc[12];
        #pragma unroll
        for (int g = 0; g < 12; ++g) acc[g] = 0ULL;

        const int k0 = kq * KQ;
        #pragma unroll 2
        for (int k = k0; k < k0 + KQ; k += 4) {
            float h0 = __ldcg(&hcur[(k + 0) * BB + b]);
            float h1 = __ldcg(&hcur[(k + 1) * BB + b]);
            float h2 = __ldcg(&hcur[(k + 2) * BB + b]);
            float h3 = __ldcg(&hcur[(k + 3) * BB + b]);
            unsigned long long ha = pack2(h0, h1);
            unsigned long long hb = pack2(h2, h3);
            #pragma unroll
            for (int g = 0; g < 12; ++g) {
                const ulonglong2 w2 = *(const ulonglong2*)&s_w[g * HH + k];
                acc[g] = fma2(ha, w2.x, acc[g]);
                acc[g] = fma2(hb, w2.y, acc[g]);
            }
        }

        if (kq) {
            float* dst = &s_red[(kq - 1) * 13 * BB + b];
            #pragma unroll
            for (int g = 0; g < 12; ++g) dst[g * BB] = red2(acc[g]);
        }
        __syncthreads();

        if (!kq) {
            float xv = x[b * TT + t];
            #pragma unroll
            for (int jj = 0; jj < COLS; ++jj) {
                float ar, az, an;
                {
                    int g0 = jj * 3;
                    ar = red2(acc[g0+0]) + s_red[0*13*BB + (g0+0)*BB + b]
                                         + s_red[1*13*BB + (g0+0)*BB + b]
                                         + s_red[2*13*BB + (g0+0)*BB + b];
                    az = red2(acc[g0+1]) + s_red[0*13*BB + (g0+1)*BB + b]
                                         + s_red[1*13*BB + (g0+1)*BB + b]
                                         + s_red[2*13*BB + (g0+1)*BB + b];
                    an = red2(acc[g0+2]) + s_red[0*13*BB + (g0+2)*BB + b]
                                         + s_red[1*13*BB + (g0+2)*BB + b]
                                         + s_red[2*13*BB + (g0+2)*BB + b];
                }
                float r = sigf(fmaf(xv, s_wi[jj * 3 + 0], s_bi[jj * 3 + 0] + s_bh[jj * 3 + 0]) + ar);
                float z = sigf(fmaf(xv, s_wi[jj * 3 + 1], s_bi[jj * 3 + 1] + s_bh[jj * 3 + 1]) + az);
                float n = tanhf(fmaf(xv, s_wi[jj * 3 + 2], s_bi[jj * 3 + 2]) + r * (an + s_bh[jj * 3 + 2]));
                float hp = __ldcg(&hcur[(j0 + jj) * BB + b]);
                hnxt[(j0 + jj) * BB + b] = (1.0f - z) * n + z * hp;
            }
        }

        grid_barrier();
        float* tc = hcur; hcur = hnxt; hnxt = tc;
    }

    // ---- swap SMEM weights to decoder ----
    for (int i = tid; i < 12 * (HH / 4); i += NTH) {
        int gl = i / (HH / 4), kk = i % (HH / 4);
        int grow = (gl % 3) * HH + (j0 + gl / 3);
        ((float4*)s_w)[gl * (HH / 4) + kk] = ((const float4*)dWh)[grow * (HH / 4) + kk];
    }
    if (tid < 12) {
        int grow = (tid % 3) * HH + (j0 + tid / 3);
        s_wi[tid] = dWi[grow];
        s_bi[tid] = dbi[grow];
        s_bh[tid] = dbh[grow];
    }
    __syncthreads();

    // ================= decoder: i = 0..512 =================
    // y_i = h_i @ lin_W.T + lin_b (redundant per CTA). Emit y_i at
    // out[:, T-i] for i>=1. For i<512 also compute h_{i+1}.
    for (int i = 0; i <= TT; ++i) {
        unsigned long long acc[13];
        #pragma unroll
        for (int g = 0; g < 13; ++g) acc[g] = 0ULL;

        const int k0 = kq * KQ;
        #pragma unroll 2
        for (int k = k0; k < k0 + KQ; k += 4) {
            float h0 = __ldcg(&hcur[(k + 0) * BB + b]);
            float h1 = __ldcg(&hcur[(k + 1) * BB + b]);
            float h2 = __ldcg(&hcur[(k + 2) * BB + b]);
            float h3 = __ldcg(&hcur[(k + 3) * BB + b]);
            unsigned long long ha = pack2(h0, h1);
            unsigned long long hb = pack2(h2, h3);
            #pragma unroll
            for (int g = 0; g < 12; ++g) {
                const ulonglong2 w2 = *(const ulonglong2*)&s_w[g * HH + k];
                acc[g] = fma2(ha, w2.x, acc[g]);
                acc[g] = fma2(hb, w2.y, acc[g]);
            }
            const ulonglong2 l2 = *(const ulonglong2*)&s_lin[k];
            acc[12] = fma2(ha, l2.x, acc[12]);
            acc[12] = fma2(hb, l2.y, acc[12]);
        }

        if (kq) {
            float* dst = &s_red[(kq - 1) * 13 * BB + b];
            #pragma unroll
            for (int g = 0; g < 13; ++g) dst[g * BB] = red2(acc[g]);
        }
        __syncthreads();

        if (!kq) {
            float y = red2(acc[12]) + s_red[0*13*BB + 12*BB + b]
                                    + s_red[1*13*BB + 12*BB + b]
                                    + s_red[2*13*BB + 12*BB + b] + s_lb;
            if (i >= 1 && blockIdx.x == 0) out[b * TT + (TT - i)] = y;
            if (i < TT) {
                #pragma unroll
                for (int jj = 0; jj < COLS; ++jj) {
                    int g0 = jj * 3;
                    float ar = red2(acc[g0+0]) + s_red[0*13*BB + (g0+0)*BB + b]
                                               + s_red[1*13*BB + (g0+0)*BB + b]
                                               + s_red[2*13*BB + (g0+0)*BB + b];
                    float az = red2(acc[g0+1]) + s_red[0*13*BB + (g0+1)*BB + b]
                                               + s_red[1*13*BB + (g0+1)*BB + b]
                                               + s_red[2*13*BB + (g0+1)*BB + b];
                    float an = red2(acc[g0+2]) + s_red[0*13*BB + (g0+2)*BB + b]
                                               + s_red[1*13*BB + (g0+2)*BB + b]
                                               + s_red[2*13*BB + (g0+2)*BB + b];
                    float r = sigf(fmaf(y, s_wi[g0 + 0], s_bi[g0 + 0] + s_bh[g0 + 0]) + ar);
                    float z = sigf(fmaf(y, s_wi[g0 + 1], s_bi[g0 + 1] + s_bh[g0 + 1]) + az);
                    float n = tanhf(fmaf(y, s_wi[g0 + 2], s_bi[g0 + 2]) + r * (an + s_bh[g0 + 2]));
                    float hp = __ldcg(&hcur[(j0 + jj) * BB + b]);
                    hnxt[(j0 + jj) * BB + b] = (1.0f - z) * n + z * hp;
                }
            }
        }

        if (i < TT) {
            grid_barrier();
            float* tc = hcur; hcur = hnxt; hnxt = tc;
        }
    }
}

extern "C" void kernel_launch(void* const* d_in, const int* in_sizes, int n_in,
                              void* d_out, int out_size) {
    gru_ae<<<NBLK, NTH>>>(
        (const float*)d_in[0],
        (const float*)d_in[1], (const float*)d_in[2],
        (const float*)d_in[3], (const float*)d_in[4],
        (const float*)d_in[5], (const float*)d_in[6],
        (const float*)d_in[7], (const float*)d_in[8],
        (const float*)d_in[9], (const float*)d_in[10],
        (float*)d_out);
}